// round 1
// baseline (speedup 1.0000x reference)
#include <cuda_runtime.h>
#include <math.h>

// Problem constants (fixed by the dataset)
#define BB 32
#define DD 512
#define KK 64
#define NN 3136          // 56*56
#define TN 64            // n-tile per block
#define NT (NN / TN)     // 49 tiles, exact

// smem strides (padded for bank-conflict-free access patterns)
#define XS_STRIDE 68     // x tile rows: 68*4B = 272B, 16B-aligned, bank-skewed
#define WS_STRIDE 65     // w chunk rows
#define AT_STRIDE 68     // alpha^T rows

#define SMEM_FLOATS (DD * XS_STRIDE + KK * WS_STRIDE + TN * AT_STRIDE)
#define SMEM_BYTES (SMEM_FLOATS * 4)

// Scratch (device globals — no allocation allowed in kernel_launch)
__device__ float g_vlad[BB * KK * DD];   // [b][k][d] raw accumulation
__device__ float g_asum[BB * KK];        // sum_n alpha[b,k,n]
__device__ float g_cnorm[BB * KK];       // 0.125 / ||column||

// ---------------------------------------------------------------------------
// Kernel 0: zero the accumulators (graph replays require re-zeroing each call)
// ---------------------------------------------------------------------------
__global__ void zero_kernel() {
    int i = blockIdx.x * blockDim.x + threadIdx.x;
    if (i < BB * KK * DD) g_vlad[i] = 0.0f;
    if (i < BB * KK)      g_asum[i] = 0.0f;
}

// ---------------------------------------------------------------------------
// Kernel 1: fused  logits-GEMM -> softmax(K) -> vlad-GEMM (atomic accumulate)
// grid = (49, 32), block = 256 threads, 1 CTA/SM (173KB smem)
// ---------------------------------------------------------------------------
__global__ void __launch_bounds__(256, 1) fused_kernel(
    const float* __restrict__ x,      // [B, D, N]
    const float* __restrict__ w,      // [K, D]
    const float* __restrict__ bias)   // [K]
{
    extern __shared__ float sm[];
    float* xs = sm;                       // [512][XS_STRIDE]  x tile (d-major)
    float* ws = xs + DD * XS_STRIDE;      // [64][WS_STRIDE]   w chunk [k][dl]
    float* at = ws + KK * WS_STRIDE;      // [64][AT_STRIDE]   logits/alpha^T [n][k]

    const int b   = blockIdx.y;
    const int n0  = blockIdx.x * TN;
    const int tid = threadIdx.x;

    // ---- load x tile: x[b, d, n0:n0+64] -> xs[d][n] (float4, coalesced) ----
    const float* xb = x + (size_t)b * DD * NN + n0;
    for (int i = tid; i < DD * (TN / 4); i += 256) {
        int d = i >> 4;
        int c = (i & 15) << 2;
        float4 v = *(const float4*)(xb + (size_t)d * NN + c);
        *(float4*)(xs + d * XS_STRIDE + c) = v;
    }

    // ---- logits GEMM: C[k][n] = sum_d w[k][d] * xs[d][n], 4x4 micro-tiles --
    const int tx = tid & 15;   // n group: n = 4*tx .. 4*tx+3
    const int ty = tid >> 4;   // k group: k = 4*ty .. 4*ty+3

    float acc[4][4];
#pragma unroll
    for (int j = 0; j < 4; ++j)
#pragma unroll
        for (int i = 0; i < 4; ++i) acc[j][i] = 0.0f;

    for (int d0 = 0; d0 < DD; d0 += 64) {
        __syncthreads();  // protect ws before overwrite (also covers xs on iter 0)
        // load w chunk [k][dl], coalesced gmem, conflict-free smem stores
        for (int i = tid; i < KK * 64; i += 256) {
            int k  = i >> 6;
            int dl = i & 63;
            ws[k * WS_STRIDE + dl] = w[k * DD + d0 + dl];
        }
        __syncthreads();

#pragma unroll 4
        for (int dl = 0; dl < 64; ++dl) {
            float4 xv = *(const float4*)(xs + (d0 + dl) * XS_STRIDE + 4 * tx);
            float a0 = ws[(4 * ty + 0) * WS_STRIDE + dl];
            float a1 = ws[(4 * ty + 1) * WS_STRIDE + dl];
            float a2 = ws[(4 * ty + 2) * WS_STRIDE + dl];
            float a3 = ws[(4 * ty + 3) * WS_STRIDE + dl];
            acc[0][0] += a0 * xv.x; acc[0][1] += a0 * xv.y; acc[0][2] += a0 * xv.z; acc[0][3] += a0 * xv.w;
            acc[1][0] += a1 * xv.x; acc[1][1] += a1 * xv.y; acc[1][2] += a1 * xv.z; acc[1][3] += a1 * xv.w;
            acc[2][0] += a2 * xv.x; acc[2][1] += a2 * xv.y; acc[2][2] += a2 * xv.z; acc[2][3] += a2 * xv.w;
            acc[3][0] += a3 * xv.x; acc[3][1] += a3 * xv.y; acc[3][2] += a3 * xv.z; acc[3][3] += a3 * xv.w;
        }
    }
    __syncthreads();

    // ---- add bias, store transposed: at[n][k] = logits[k][n] + bias[k] -----
    {
        float bv0 = bias[4 * ty + 0];
        float bv1 = bias[4 * ty + 1];
        float bv2 = bias[4 * ty + 2];
        float bv3 = bias[4 * ty + 3];
#pragma unroll
        for (int i = 0; i < 4; ++i) {
            float* dst = at + (4 * tx + i) * AT_STRIDE + 4 * ty;
            dst[0] = acc[0][i] + bv0;
            dst[1] = acc[1][i] + bv1;
            dst[2] = acc[2][i] + bv2;
            dst[3] = acc[3][i] + bv3;
        }
    }
    __syncthreads();

    // ---- softmax over k for each pixel n (row of at) -----------------------
    if (tid < TN) {
        float* row = at + tid * AT_STRIDE;
        float m = row[0];
#pragma unroll 8
        for (int k = 1; k < KK; ++k) m = fmaxf(m, row[k]);
        float s = 0.0f;
#pragma unroll 8
        for (int k = 0; k < KK; ++k) {
            float e = __expf(row[k] - m);
            row[k] = e;
            s += e;
        }
        float inv = 1.0f / s;
#pragma unroll 8
        for (int k = 0; k < KK; ++k) row[k] *= inv;
    }
    __syncthreads();

    // ---- per-tile sum_n alpha[k][n] -> asum[b][k] ---------------------------
    if (tid < KK) {
        float s = 0.0f;
#pragma unroll 8
        for (int n = 0; n < TN; ++n) s += at[n * AT_STRIDE + tid];
        atomicAdd(&g_asum[b * KK + tid], s);
    }

    // ---- vlad GEMM: raw[b][k][d] += sum_n at[n][k] * xs[d][n] ---------------
    const int kx = tid & 15;   // k group: k = 4*kx .. +3
    const int dy = tid >> 4;   // d base within 64-group: 4*dy
    float* vb = g_vlad + (size_t)b * KK * DD;

    for (int dd = 0; dd < 8; ++dd) {
        const int d = dd * 64 + 4 * dy;   // warp-mates differ by Δd=4 -> no bank conflict
        float vacc[4][4];
#pragma unroll
        for (int j = 0; j < 4; ++j)
#pragma unroll
            for (int i = 0; i < 4; ++i) vacc[j][i] = 0.0f;

#pragma unroll 4
        for (int n = 0; n < TN; ++n) {
            float4 av = *(const float4*)(at + n * AT_STRIDE + 4 * kx);
            float x0 = xs[(d + 0) * XS_STRIDE + n];
            float x1 = xs[(d + 1) * XS_STRIDE + n];
            float x2 = xs[(d + 2) * XS_STRIDE + n];
            float x3 = xs[(d + 3) * XS_STRIDE + n];
            vacc[0][0] += av.x * x0; vacc[0][1] += av.x * x1; vacc[0][2] += av.x * x2; vacc[0][3] += av.x * x3;
            vacc[1][0] += av.y * x0; vacc[1][1] += av.y * x1; vacc[1][2] += av.y * x2; vacc[1][3] += av.y * x3;
            vacc[2][0] += av.z * x0; vacc[2][1] += av.z * x1; vacc[2][2] += av.z * x2; vacc[2][3] += av.z * x3;
            vacc[3][0] += av.w * x0; vacc[3][1] += av.w * x1; vacc[3][2] += av.w * x2; vacc[3][3] += av.w * x3;
        }
#pragma unroll
        for (int j = 0; j < 4; ++j)
#pragma unroll
            for (int i = 0; i < 4; ++i)
                atomicAdd(vb + (size_t)(4 * kx + j) * DD + d + i, vacc[j][i]);
    }
}

// ---------------------------------------------------------------------------
// Kernel 2: per-(b,k) column norm of y = raw - centers*asum
// grid = (K, B), block = 128
// ---------------------------------------------------------------------------
__global__ void colnorm_kernel(const float* __restrict__ centers)   // [D, K]
{
    const int k = blockIdx.x, b = blockIdx.y;
    const int tid = threadIdx.x;
    const float a = g_asum[b * KK + k];
    const float* vb = g_vlad + (size_t)(b * KK + k) * DD;

    float s = 0.0f;
    for (int d = tid; d < DD; d += 128) {
        float y = vb[d] - centers[d * KK + k] * a;
        s += y * y;
    }
#pragma unroll
    for (int off = 16; off > 0; off >>= 1) s += __shfl_xor_sync(0xFFFFFFFFu, s, off);

    __shared__ float red[4];
    if ((tid & 31) == 0) red[tid >> 5] = s;
    __syncthreads();
    if (tid == 0) {
        float t = red[0] + red[1] + red[2] + red[3];
        // global norm after intra-normalization is exactly sqrt(K)=8 up to
        // O(1e-7) rounding -> fold 1/8 into the per-column scale.
        g_cnorm[b * KK + k] = 0.125f * rsqrtf(t);
    }
}

// ---------------------------------------------------------------------------
// Kernel 3: finalize  out[b, d*K + k] = (raw - centers*asum) * cnorm
// ---------------------------------------------------------------------------
__global__ void finalize_kernel(const float* __restrict__ centers,
                                float* __restrict__ out)
{
    int t = blockIdx.x * blockDim.x + threadIdx.x;
    if (t >= BB * DD * KK) return;
    int b   = t >> 15;          // D*K = 32768
    int rem = t & 32767;
    int d   = rem >> 6;
    int k   = rem & 63;
    float a = g_asum[b * KK + k];
    float y = g_vlad[(size_t)(b * KK + k) * DD + d] - centers[d * KK + k] * a;
    out[t] = y * g_cnorm[b * KK + k];
}

// ---------------------------------------------------------------------------
extern "C" void kernel_launch(void* const* d_in, const int* in_sizes, int n_in,
                              void* d_out, int out_size) {
    const float* x       = (const float*)d_in[0];   // [32,512,56,56]
    const float* w       = (const float*)d_in[1];   // [64,512]
    const float* bias    = (const float*)d_in[2];   // [64]
    const float* centers = (const float*)d_in[3];   // [512,64]
    float* out = (float*)d_out;                     // [32, 512*64]

    cudaFuncSetAttribute(fused_kernel,
                         cudaFuncAttributeMaxDynamicSharedMemorySize, SMEM_BYTES);

    zero_kernel<<<(BB * KK * DD + 255) / 256, 256>>>();

    dim3 g1(NT, BB);
    fused_kernel<<<g1, 256, SMEM_BYTES>>>(x, w, bias);

    colnorm_kernel<<<dim3(KK, BB), 128>>>(centers);

    finalize_kernel<<<(BB * DD * KK + 255) / 256, 256>>>(centers, out);
}

// round 3
// speedup vs baseline: 1.8409x; 1.8409x over previous
#include <cuda_runtime.h>
#include <cstdint>
#include <math.h>

// ---------------- problem constants ----------------
#define BB 32
#define DD 512
#define KK 64
#define NNPIX 3136
#define TNP 64              // pixels per tile
#define NTILES 49           // 3136/64
#define CPB 4               // CTAs per batch
#define THREADS 256

// ---------------- smem layout (floats) ----------------
#define XS_STRIDE 72        // [512][72]  x tile (fp32 bits, fed as tf32)
#define WS_STRIDE 68        // [64][68]   w d-chunk
#define AT_STRIDE 72        // [64][72]   logits/alpha [n][k]
#define XS_FLOATS (DD * XS_STRIDE)
#define WS_FLOATS (KK * WS_STRIDE)
#define AT_FLOATS (TNP * AT_STRIDE)
#define SMEM_FLOATS (XS_FLOATS + WS_FLOATS + AT_FLOATS)
#define SMEM_BYTES (SMEM_FLOATS * 4)

// ---------------- device scratch ----------------
__device__ float g_part[BB * CPB * DD * KK];   // [cta][d][k] partial vlads
__device__ float g_asum[BB * KK];
__device__ float g_cnorm[BB * KK];
__device__ float g_y[BB * DD * KK];            // un-normalized vlad [b][d][k]

// m16n8k8 tf32 mma: D = A@B + D. A row-major, B col-major fragments.
static __device__ __forceinline__ void mma_tf32(float c[4],
        float a0, float a1, float a2, float a3, float b0, float b1) {
    asm volatile(
        "mma.sync.aligned.m16n8k8.row.col.f32.tf32.tf32.f32 "
        "{%0,%1,%2,%3}, {%4,%5,%6,%7}, {%8,%9}, {%0,%1,%2,%3};"
        : "+f"(c[0]), "+f"(c[1]), "+f"(c[2]), "+f"(c[3])
        : "r"(__float_as_uint(a0)), "r"(__float_as_uint(a1)),
          "r"(__float_as_uint(a2)), "r"(__float_as_uint(a3)),
          "r"(__float_as_uint(b0)), "r"(__float_as_uint(b1)));
}

// ---------------------------------------------------------------------------
__global__ void zero_kernel() {
    int i = blockIdx.x * blockDim.x + threadIdx.x;
    if (i < BB * KK) g_asum[i] = 0.0f;
}

// ---------------------------------------------------------------------------
// Fused kernel. grid = 128 (b*4+q), block = 256, 1 CTA/SM.
// Per tile (64 pixels): load x -> GEMM1 (logits) -> softmax -> GEMM2 (vlad,
// accumulated in registers across tiles). Epilogue stores vlad partials once.
// ---------------------------------------------------------------------------
__global__ void __launch_bounds__(THREADS, 1) fused_kernel(
    const float* __restrict__ x,      // [B, D, N]
    const float* __restrict__ w,      // [K, D]
    const float* __restrict__ bias)   // [K]
{
    extern __shared__ float sm[];
    float* xs = sm;                   // [512][72]
    float* ws = xs + XS_FLOATS;       // [64][68]
    float* at = ws + WS_FLOATS;       // [64][72]

    const int tid  = threadIdx.x;
    const int wid  = tid >> 5;
    const int lane = tid & 31;
    const int g    = lane >> 2;       // group id 0..7
    const int tig  = lane & 3;        // thread-in-group 0..3
    const int b    = blockIdx.x >> 2;
    const int q    = blockIdx.x & 3;

    // GEMM1 warp mapping: k-tile row (16 k) and n half (32 n)
    const int kb = (wid & 3) * 16;
    const int nb = (wid >> 2) * 32;
    const float bg  = bias[kb + g];
    const float bg8 = bias[kb + g + 8];

    // GEMM2 warp mapping: each warp owns d in [wid*64, wid*64+64), all 64 k
    const int db = wid * 64;

    // persistent vlad accumulators: [4 m-tiles][8 n-tiles][4]
    float c2[4][8][4];
#pragma unroll
    for (int mt = 0; mt < 4; ++mt)
#pragma unroll
        for (int nt = 0; nt < 8; ++nt)
#pragma unroll
            for (int r = 0; r < 4; ++r) c2[mt][nt][r] = 0.0f;

    float asum_acc = 0.0f;

    for (int t = q; t < NTILES; t += CPB) {
        __syncthreads();   // previous tile's readers of xs/at are done

        // ---- load x tile [512][64] -> xs ---------------------------------
        const float* xb = x + (size_t)b * DD * NNPIX + t * TNP;
        for (int i = tid; i < DD * (TNP / 4); i += THREADS) {
            int d = i >> 4;
            int j = i & 15;
            float4 v = *(const float4*)(xb + (size_t)d * NNPIX + j * 4);
            *(float4*)(xs + d * XS_STRIDE + j * 4) = v;
        }

        // ---- GEMM1: logits[64k][64n] = w @ x ------------------------------
        float c1[4][4];
#pragma unroll
        for (int jt = 0; jt < 4; ++jt)
#pragma unroll
            for (int r = 0; r < 4; ++r) c1[jt][r] = 0.0f;

        for (int dc = 0; dc < 8; ++dc) {
            __syncthreads();   // prev ws readers done (dc=0: also orders nothing harmful)
            // stage w chunk [64k][64d]
            for (int i = tid; i < KK * 16; i += THREADS) {
                int k = i >> 4;
                int j = i & 15;
                float4 v = *(const float4*)(w + (size_t)k * DD + dc * 64 + j * 4);
                *(float4*)(ws + k * WS_STRIDE + j * 4) = v;
            }
            __syncthreads();   // ws ready; also xs ready at dc=0

#pragma unroll
            for (int ds = 0; ds < 8; ++ds) {
                const int dd = ds * 8;
                float a0 = ws[(kb + g) * WS_STRIDE + dd + tig];
                float a1 = ws[(kb + g + 8) * WS_STRIDE + dd + tig];
                float a2 = ws[(kb + g) * WS_STRIDE + dd + tig + 4];
                float a3 = ws[(kb + g + 8) * WS_STRIDE + dd + tig + 4];
                const int drow = dc * 64 + dd;
#pragma unroll
                for (int jt = 0; jt < 4; ++jt) {
                    float b0 = xs[(drow + tig) * XS_STRIDE + nb + jt * 8 + g];
                    float b1 = xs[(drow + tig + 4) * XS_STRIDE + nb + jt * 8 + g];
                    mma_tf32(c1[jt], a0, a1, a2, a3, b0, b1);
                }
            }
        }
        __syncthreads();   // GEMM1 reads of at-region? none; this orders at writes below

        // ---- bias + transpose store: at[n][k] = logits[k][n] + bias[k] ----
#pragma unroll
        for (int jt = 0; jt < 4; ++jt) {
            int n0 = nb + jt * 8 + 2 * tig;
            at[n0 * AT_STRIDE + kb + g]           = c1[jt][0] + bg;
            at[(n0 + 1) * AT_STRIDE + kb + g]     = c1[jt][1] + bg;
            at[n0 * AT_STRIDE + kb + g + 8]       = c1[jt][2] + bg8;
            at[(n0 + 1) * AT_STRIDE + kb + g + 8] = c1[jt][3] + bg8;
        }
        __syncthreads();

        // ---- softmax over k per pixel; write tf32-truncated alpha ---------
        if (tid < TNP) {
            float* row = at + tid * AT_STRIDE;
            float m = -1e30f;
#pragma unroll 8
            for (int j = 0; j < KK; ++j) m = fmaxf(m, row[(j + tid) & 63]);
            float s = 0.0f;
#pragma unroll 8
            for (int j = 0; j < KK; ++j) {
                int kk = (j + tid) & 63;
                float e = __expf(row[kk] - m);
                row[kk] = e;
                s += e;
            }
            float inv = 1.0f / s;
#pragma unroll 8
            for (int j = 0; j < KK; ++j) {
                int kk = (j + tid) & 63;
                float v = row[kk] * inv;
                row[kk] = __uint_as_float(__float_as_uint(v) & 0xFFFFE000u);
            }
        }
        __syncthreads();

        // ---- asum accumulate (reads the same truncated alpha GEMM2 uses) --
        if (tid < KK) {
            float s = 0.0f;
#pragma unroll 8
            for (int n = 0; n < TNP; ++n) s += at[n * AT_STRIDE + tid];
            asum_acc += s;
        }

        // ---- GEMM2: vlad[d][k] += x[d][n] @ alpha[n][k] --------------------
#pragma unroll
        for (int ks = 0; ks < 8; ++ks) {
            const int nn = ks * 8;
            float b0[8], b1[8];
#pragma unroll
            for (int nt = 0; nt < 8; ++nt) {
                b0[nt] = at[(nn + tig) * AT_STRIDE + nt * 8 + g];
                b1[nt] = at[(nn + tig + 4) * AT_STRIDE + nt * 8 + g];
            }
#pragma unroll
            for (int mt = 0; mt < 4; ++mt) {
                const int dr = db + mt * 16;
                float a0 = xs[(dr + g) * XS_STRIDE + nn + tig];
                float a1 = xs[(dr + g + 8) * XS_STRIDE + nn + tig];
                float a2 = xs[(dr + g) * XS_STRIDE + nn + tig + 4];
                float a3 = xs[(dr + g + 8) * XS_STRIDE + nn + tig + 4];
#pragma unroll
                for (int nt = 0; nt < 8; ++nt)
                    mma_tf32(c2[mt][nt], a0, a1, a2, a3, b0[nt], b1[nt]);
            }
        }
    }

    if (tid < KK) atomicAdd(&g_asum[b * KK + tid], asum_acc);

    // ---- epilogue: store vlad partials [d][k] --------------------------------
    float* dst = g_part + (size_t)blockIdx.x * DD * KK;
#pragma unroll
    for (int mt = 0; mt < 4; ++mt) {
#pragma unroll
        for (int nt = 0; nt < 8; ++nt) {
            int d0 = db + mt * 16 + g;
            int k0 = nt * 8 + 2 * tig;
            float2 v0 = { c2[mt][nt][0], c2[mt][nt][1] };
            float2 v1 = { c2[mt][nt][2], c2[mt][nt][3] };
            *(float2*)(dst + (size_t)d0 * KK + k0)       = v0;
            *(float2*)(dst + (size_t)(d0 + 8) * KK + k0) = v1;
        }
    }
}

// ---------------------------------------------------------------------------
// colnorm: y[b][d][k] = sum_q part - centers*asum ; cnorm = 0.125*rsqrt(sum_d y^2)
// ---------------------------------------------------------------------------
__global__ void colnorm_kernel(const float* __restrict__ centers) {
    const int b = blockIdx.x;
    const int k = threadIdx.x & 63;
    const int gg = threadIdx.x >> 6;
    const float a = g_asum[b * KK + k];

    float s = 0.0f;
    for (int d = gg; d < DD; d += 4) {
        size_t o = (size_t)d * KK + k;
        float y = g_part[((size_t)(b * 4 + 0) * DD) * KK + o]
                + g_part[((size_t)(b * 4 + 1) * DD) * KK + o]
                + g_part[((size_t)(b * 4 + 2) * DD) * KK + o]
                + g_part[((size_t)(b * 4 + 3) * DD) * KK + o]
                - centers[d * KK + k] * a;
        g_y[((size_t)b * DD + d) * KK + k] = y;
        s += y * y;
    }
    __shared__ float red[4][KK];
    red[gg][k] = s;
    __syncthreads();
    if (threadIdx.x < KK) {
        float t = red[0][k] + red[1][k] + red[2][k] + red[3][k];
        // global L2 norm after intra-normalization == sqrt(K) = 8 (to fp32 eps)
        g_cnorm[b * KK + k] = 0.125f * rsqrtf(t);
    }
}

// ---------------------------------------------------------------------------
__global__ void finalize_kernel(float* __restrict__ out) {
    int i = blockIdx.x * blockDim.x + threadIdx.x;
    if (i >= BB * DD * KK) return;
    int b = i >> 15;
    int k = i & 63;
    out[i] = g_y[i] * g_cnorm[b * KK + k];
}

// ---------------------------------------------------------------------------
extern "C" void kernel_launch(void* const* d_in, const int* in_sizes, int n_in,
                              void* d_out, int out_size) {
    const float* x       = (const float*)d_in[0];
    const float* w       = (const float*)d_in[1];
    const float* bias    = (const float*)d_in[2];
    const float* centers = (const float*)d_in[3];
    float* out = (float*)d_out;

    cudaFuncSetAttribute(fused_kernel,
                         cudaFuncAttributeMaxDynamicSharedMemorySize, SMEM_BYTES);

    zero_kernel<<<(BB * KK + 255) / 256, 256>>>();
    fused_kernel<<<BB * CPB, THREADS, SMEM_BYTES>>>(x, w, bias);
    colnorm_kernel<<<BB, 256>>>(centers);
    finalize_kernel<<<(BB * DD * KK + 255) / 256, 256>>>(out);
}

// round 4
// speedup vs baseline: 2.9505x; 1.6027x over previous
#include <cuda_runtime.h>
#include <cstdint>
#include <math.h>

// ---------------- problem constants ----------------
#define BB 32
#define DD 512
#define KK 64
#define NNPIX 3136
#define TNP 64              // pixels per tile
#define NTILES 49           // 3136/64
#define CPB 4               // CTAs per batch
#define THREADS 512

// ---------------- smem layout (floats) ----------------
#define XS_STRIDE 72
#define WS_STRIDE 68
#define AT_STRIDE 72
#define XS_FLOATS (DD * XS_STRIDE)       // 36864
#define WS_FLOATS (KK * WS_STRIDE)       // 4352
#define AT_FLOATS (TNP * AT_STRIDE)      // 4608
#define ASR_FLOATS (8 * 72)              // 576
#define SMEM_FLOATS (XS_FLOATS + WS_FLOATS + AT_FLOATS + ASR_FLOATS)
#define SMEM_BYTES (SMEM_FLOATS * 4)     // 185600

// ---------------- device scratch ----------------
__device__ float g_part[BB * CPB * DD * KK];    // [cta][d][k]
__device__ float g_asum_part[BB * CPB * KK];    // [cta][k]

// m16n8k8 tf32 mma: D = A@B + D. A row-major frag, B col-major frag.
static __device__ __forceinline__ void mma_tf32(float c[4],
        float a0, float a1, float a2, float a3, float b0, float b1) {
    asm volatile(
        "mma.sync.aligned.m16n8k8.row.col.f32.tf32.tf32.f32 "
        "{%0,%1,%2,%3}, {%4,%5,%6,%7}, {%8,%9}, {%0,%1,%2,%3};"
        : "+f"(c[0]), "+f"(c[1]), "+f"(c[2]), "+f"(c[3])
        : "r"(__float_as_uint(a0)), "r"(__float_as_uint(a1)),
          "r"(__float_as_uint(a2)), "r"(__float_as_uint(a3)),
          "r"(__float_as_uint(b0)), "r"(__float_as_uint(b1)));
}

static __device__ __forceinline__ uint32_t smem_u32(const void* p) {
    uint32_t a;
    asm("{ .reg .u64 t; cvta.to.shared.u64 t, %1; cvt.u32.u64 %0, t; }" : "=r"(a) : "l"(p));
    return a;
}
static __device__ __forceinline__ void cp16(uint32_t dst, const void* src) {
    asm volatile("cp.async.cg.shared.global [%0], [%1], 16;" :: "r"(dst), "l"(src));
}
#define CP_COMMIT() asm volatile("cp.async.commit_group;" ::: "memory")
#define CP_WAIT0()  asm volatile("cp.async.wait_group 0;" ::: "memory")

static __device__ __forceinline__ float trunc_tf32(float v) {
    return __uint_as_float(__float_as_uint(v) & 0xFFFFE000u);
}

// ---------------------------------------------------------------------------
// Fused kernel. grid = 128 (b*4+q), block = 512, 1 CTA/SM.
// ---------------------------------------------------------------------------
__global__ void __launch_bounds__(THREADS, 1) fused_kernel(
    const float* __restrict__ x,      // [B, D, N]
    const float* __restrict__ w,      // [K, D]
    const float* __restrict__ bias)   // [K]
{
    extern __shared__ float sm[];
    float* xs    = sm;                       // [512][72]
    float* ws    = xs + XS_FLOATS;           // [64][68]
    float* at    = ws + WS_FLOATS;           // [64][72]
    float* asred = at + AT_FLOATS;           // [8][72]
    const uint32_t xs_u = smem_u32(xs);
    const uint32_t ws_u = smem_u32(ws);

    const int tid  = threadIdx.x;
    const int wid  = tid >> 5;               // 0..15
    const int lane = tid & 31;
    const int g    = lane >> 2;              // 0..7
    const int tig  = lane & 3;               // 0..3
    const int b    = blockIdx.x >> 2;
    const int q    = blockIdx.x & 3;

    // GEMM1 warp mapping: 16k x 16n per warp
    const int kb = (wid & 3) * 16;
    const int nb = (wid >> 2) * 16;
    const float bg  = bias[kb + g];
    const float bg8 = bias[kb + g + 8];

    // GEMM2 warp mapping: each warp owns 32 d (2 m-tiles), all 64 k
    const int db = wid * 32;

    // persistent vlad accumulators: [2 m][8 n][4] = 64 regs
    float c2[2][8][4];
#pragma unroll
    for (int mt = 0; mt < 2; ++mt)
#pragma unroll
        for (int nt = 0; nt < 8; ++nt)
#pragma unroll
            for (int r = 0; r < 4; ++r) c2[mt][nt][r] = 0.0f;

    float asum_acc = 0.0f;

    for (int t = q; t < NTILES; t += CPB) {
        __syncthreads();   // prev tile's readers of xs/at done

        // ---- x tile [512][64] -> xs via cp.async (16 x 16B per thread) ----
        const float* xb = x + (size_t)b * DD * NNPIX + t * TNP;
#pragma unroll
        for (int r = 0; r < 16; ++r) {
            int i = tid + r * THREADS;       // 0..8191
            int d = i >> 4;
            int j = i & 15;
            cp16(xs_u + (uint32_t)(d * XS_STRIDE + j * 4) * 4,
                 xb + (size_t)d * NNPIX + j * 4);
        }
        CP_COMMIT();

        // ---- GEMM1: logits[64k][64n] = w @ x -------------------------------
        float c1[2][4];
#pragma unroll
        for (int nt = 0; nt < 2; ++nt)
#pragma unroll
            for (int r = 0; r < 4; ++r) c1[nt][r] = 0.0f;

        for (int dc = 0; dc < 8; ++dc) {
            __syncthreads();                 // prev ws readers done
#pragma unroll
            for (int r = 0; r < 2; ++r) {    // w chunk: 1024 x 16B
                int i = tid + r * THREADS;
                int k = i >> 4;
                int j = i & 15;
                cp16(ws_u + (uint32_t)(k * WS_STRIDE + j * 4) * 4,
                     w + (size_t)k * DD + dc * 64 + j * 4);
            }
            CP_COMMIT();
            CP_WAIT0();                      // dc=0 also waits for the x tile
            __syncthreads();

#pragma unroll
            for (int ds = 0; ds < 8; ++ds) {
                const int dd = ds * 8;
                const int drow = dc * 64 + dd;
                float a0 = ws[(kb + g) * WS_STRIDE + dd + tig];
                float a1 = ws[(kb + g + 8) * WS_STRIDE + dd + tig];
                float a2 = ws[(kb + g) * WS_STRIDE + dd + tig + 4];
                float a3 = ws[(kb + g + 8) * WS_STRIDE + dd + tig + 4];
#pragma unroll
                for (int nt = 0; nt < 2; ++nt) {
                    float b0 = xs[(drow + tig) * XS_STRIDE + nb + nt * 8 + g];
                    float b1 = xs[(drow + tig + 4) * XS_STRIDE + nb + nt * 8 + g];
                    mma_tf32(c1[nt], a0, a1, a2, a3, b0, b1);
                }
            }
        }

        // ---- bias + transpose store to at[n][k] (at free: no readers now) --
#pragma unroll
        for (int nt = 0; nt < 2; ++nt) {
            int n0 = nb + nt * 8 + 2 * tig;
            at[n0 * AT_STRIDE + kb + g]           = c1[nt][0] + bg;
            at[(n0 + 1) * AT_STRIDE + kb + g]     = c1[nt][1] + bg;
            at[n0 * AT_STRIDE + kb + g + 8]       = c1[nt][2] + bg8;
            at[(n0 + 1) * AT_STRIDE + kb + g + 8] = c1[nt][3] + bg8;
        }
        __syncthreads();

        // ---- softmax over k per pixel: warp wid -> pixels wid*4..+3 --------
#pragma unroll
        for (int pp = 0; pp < 4; ++pp) {
            int p = wid * 4 + pp;
            float v0 = at[p * AT_STRIDE + lane];
            float v1 = at[p * AT_STRIDE + lane + 32];
            float m = fmaxf(v0, v1);
#pragma unroll
            for (int off = 16; off > 0; off >>= 1)
                m = fmaxf(m, __shfl_xor_sync(0xFFFFFFFFu, m, off));
            float e0 = __expf(v0 - m);
            float e1 = __expf(v1 - m);
            float s = e0 + e1;
#pragma unroll
            for (int off = 16; off > 0; off >>= 1)
                s += __shfl_xor_sync(0xFFFFFFFFu, s, off);
            float inv = 1.0f / s;
            at[p * AT_STRIDE + lane]      = trunc_tf32(e0 * inv);
            at[p * AT_STRIDE + lane + 32] = trunc_tf32(e1 * inv);
        }
        __syncthreads();

        // ---- asum partial: thread (k = tid&63, grp = tid>>6) sums 8 pixels --
        {
            int k = tid & 63;
            int grp = tid >> 6;
            float s = 0.0f;
#pragma unroll
            for (int i = 0; i < 8; ++i) s += at[(grp * 8 + i) * AT_STRIDE + k];
            asred[grp * 72 + k] = s;
        }
        __syncthreads();
        if (tid < KK) {
            float s = 0.0f;
#pragma unroll
            for (int i = 0; i < 8; ++i) s += asred[i * 72 + tid];
            asum_acc += s;
        }

        // ---- GEMM2: vlad[d][k] += x[d][n] @ alpha[n][k] ---------------------
#pragma unroll
        for (int ks = 0; ks < 8; ++ks) {
            const int nn = ks * 8;
            float b0[8], b1[8];
#pragma unroll
            for (int nt = 0; nt < 8; ++nt) {
                b0[nt] = at[(nn + tig) * AT_STRIDE + nt * 8 + g];
                b1[nt] = at[(nn + tig + 4) * AT_STRIDE + nt * 8 + g];
            }
#pragma unroll
            for (int mt = 0; mt < 2; ++mt) {
                const int dr = db + mt * 16;
                float a0 = xs[(dr + g) * XS_STRIDE + nn + tig];
                float a1 = xs[(dr + g + 8) * XS_STRIDE + nn + tig];
                float a2 = xs[(dr + g) * XS_STRIDE + nn + tig + 4];
                float a3 = xs[(dr + g + 8) * XS_STRIDE + nn + tig + 4];
#pragma unroll
                for (int nt = 0; nt < 8; ++nt)
                    mma_tf32(c2[mt][nt], a0, a1, a2, a3, b0[nt], b1[nt]);
            }
        }
    }

    if (tid < KK) g_asum_part[blockIdx.x * KK + tid] = asum_acc;

    // ---- epilogue: smem-staged coalesced store of vlad partials -------------
    float* stage = xs;   // reuse x-tile region: [128][72]
    float* dstb = g_part + (size_t)blockIdx.x * DD * KK;
    for (int chunk = 0; chunk < 4; ++chunk) {
        __syncthreads();
        if ((wid >> 2) == chunk) {
            int lw = wid & 3;
#pragma unroll
            for (int mt = 0; mt < 2; ++mt) {
                int lrow = lw * 32 + mt * 16 + g;
#pragma unroll
                for (int nt = 0; nt < 8; ++nt) {
                    int k0 = nt * 8 + 2 * tig;
                    *(float2*)&stage[lrow * 72 + k0]       = make_float2(c2[mt][nt][0], c2[mt][nt][1]);
                    *(float2*)&stage[(lrow + 8) * 72 + k0] = make_float2(c2[mt][nt][2], c2[mt][nt][3]);
                }
            }
        }
        __syncthreads();
        float* dst = dstb + (size_t)chunk * 128 * KK;
#pragma unroll
        for (int r = 0; r < 4; ++r) {
            int i = tid + r * THREADS;       // 0..2047 float4s
            int dl = i >> 4;
            int k4 = (i & 15) * 4;
            float4 v = *(float4*)&stage[dl * 72 + k4];
            *(float4*)&dst[(size_t)dl * KK + k4] = v;
        }
    }
}

// ---------------------------------------------------------------------------
// Merged colnorm + finalize. grid = 32 (b), block = 256.
// y[d][k] = sum_q part - centers*asum ; out = y * 0.125 * rsqrt(sum_d y^2)
// ---------------------------------------------------------------------------
#define CF_SMEM ((DD * KK + 4 * KK + KK) * 4)
__global__ void colnorm_finalize_kernel(const float* __restrict__ centers,
                                        float* __restrict__ out)
{
    extern __shared__ float cfs[];
    float* ys   = cfs;               // [512][64]
    float* red  = ys + DD * KK;      // [4][64]
    float* cns  = red + 4 * KK;      // [64]

    const int b  = blockIdx.x;
    const int k  = threadIdx.x & 63;
    const int gg = threadIdx.x >> 6; // 0..3

    float a = g_asum_part[(b * 4 + 0) * KK + k]
            + g_asum_part[(b * 4 + 1) * KK + k]
            + g_asum_part[(b * 4 + 2) * KK + k]
            + g_asum_part[(b * 4 + 3) * KK + k];

    const float* p0 = g_part + (size_t)(b * 4 + 0) * DD * KK;
    const float* p1 = g_part + (size_t)(b * 4 + 1) * DD * KK;
    const float* p2 = g_part + (size_t)(b * 4 + 2) * DD * KK;
    const float* p3 = g_part + (size_t)(b * 4 + 3) * DD * KK;

    float s = 0.0f;
    for (int d = gg; d < DD; d += 4) {
        size_t o = (size_t)d * KK + k;
        float y = p0[o] + p1[o] + p2[o] + p3[o] - centers[d * KK + k] * a;
        ys[d * KK + k] = y;
        s += y * y;
    }
    red[gg * KK + k] = s;
    __syncthreads();
    if (threadIdx.x < KK) {
        float tsum = red[k] + red[KK + k] + red[2 * KK + k] + red[3 * KK + k];
        // global L2 norm after intra-normalization == sqrt(K) = 8 (to fp32 eps)
        cns[k] = 0.125f * rsqrtf(tsum);
    }
    __syncthreads();

    float* ob = out + (size_t)b * DD * KK;
#pragma unroll
    for (int r = 0; r < 32; ++r) {
        int i = threadIdx.x + r * 256;           // 0..8191 float4s
        int k4 = (i & 15) * 4;
        float4 v = *(float4*)&ys[i * 4];
        v.x *= cns[k4];
        v.y *= cns[k4 + 1];
        v.z *= cns[k4 + 2];
        v.w *= cns[k4 + 3];
        *(float4*)&ob[(size_t)i * 4] = v;
    }
}

// ---------------------------------------------------------------------------
extern "C" void kernel_launch(void* const* d_in, const int* in_sizes, int n_in,
                              void* d_out, int out_size) {
    const float* x       = (const float*)d_in[0];
    const float* w       = (const float*)d_in[1];
    const float* bias    = (const float*)d_in[2];
    const float* centers = (const float*)d_in[3];
    float* out = (float*)d_out;

    cudaFuncSetAttribute(fused_kernel,
                         cudaFuncAttributeMaxDynamicSharedMemorySize, SMEM_BYTES);
    cudaFuncSetAttribute(colnorm_finalize_kernel,
                         cudaFuncAttributeMaxDynamicSharedMemorySize, CF_SMEM);

    fused_kernel<<<BB * CPB, THREADS, SMEM_BYTES>>>(x, w, bias);
    colnorm_finalize_kernel<<<BB, 256, CF_SMEM>>>(centers, out);
}